// round 17
// baseline (speedup 1.0000x reference)
#include <cuda_runtime.h>

// heightfield: [16,1,512,512] f32 -> same shape.
// out[w] = 1 - clip( max_{r=1..16}( pad(row)[w+r] - r/10 ) - row[w], 0, 1 )
// R14 dual-chain engine (tied-best wall): each thread processes the SAME
// column quad in two image halves -> 10 independent LDG.128, shared pad
// logic, two interleaved max trees. Single change vs R14: stores use
// st.global.wt (write-through) to probe the output write-drain ceiling.

#define IM 512
#define NEG (-1e30f)
#define THREADS 256
#define HALF (4194304 / 2)             // element offset between the two tasks

__global__ __launch_bounds__(THREADS) void shadow_dualwt(const float* __restrict__ in,
                                                         float* __restrict__ out) {
    const int gtid = blockIdx.x * THREADS + threadIdx.x;
    const int c0 = gtid << 2;              // element index in first half
    const int col = c0 & (IM - 1);         // column (same for both halves)

    const float* pa = in + c0;
    const float* pb = in + c0 + HALF;

    float ga[20], gb[20];
    // Warp spans 128 aligned columns; only wbase==384 warps can reach the pad.
    if (col < 384) {
        #pragma unroll
        for (int i = 0; i < 5; ++i) {
            float4 va = *reinterpret_cast<const float4*>(pa + 4 * i);
            float4 vb = *reinterpret_cast<const float4*>(pb + 4 * i);
            ga[4*i+0] = va.x - 0.1f * (4*i+0);
            ga[4*i+1] = va.y - 0.1f * (4*i+1);
            ga[4*i+2] = va.z - 0.1f * (4*i+2);
            ga[4*i+3] = va.w - 0.1f * (4*i+3);
            gb[4*i+0] = vb.x - 0.1f * (4*i+0);
            gb[4*i+1] = vb.y - 0.1f * (4*i+1);
            gb[4*i+2] = vb.z - 0.1f * (4*i+2);
            gb[4*i+3] = vb.w - 0.1f * (4*i+3);
        }
    } else {
        float4 va0 = *reinterpret_cast<const float4*>(pa);
        float4 vb0 = *reinterpret_cast<const float4*>(pb);
        ga[0] = va0.x; ga[1] = va0.y - 0.1f; ga[2] = va0.z - 0.2f; ga[3] = va0.w - 0.3f;
        gb[0] = vb0.x; gb[1] = vb0.y - 0.1f; gb[2] = vb0.z - 0.2f; gb[3] = vb0.w - 0.3f;
        #pragma unroll
        for (int i = 1; i < 5; ++i) {
            if (col + 4 * i <= IM - 4) {
                float4 va = *reinterpret_cast<const float4*>(pa + 4 * i);
                float4 vb = *reinterpret_cast<const float4*>(pb + 4 * i);
                ga[4*i+0] = va.x - 0.1f * (4*i+0);
                ga[4*i+1] = va.y - 0.1f * (4*i+1);
                ga[4*i+2] = va.z - 0.1f * (4*i+2);
                ga[4*i+3] = va.w - 0.1f * (4*i+3);
                gb[4*i+0] = vb.x - 0.1f * (4*i+0);
                gb[4*i+1] = vb.y - 0.1f * (4*i+1);
                gb[4*i+2] = vb.z - 0.1f * (4*i+2);
                gb[4*i+3] = vb.w - 0.1f * (4*i+3);
            } else {                       // beyond row end: never wins
                ga[4*i+0] = NEG; ga[4*i+1] = NEG; ga[4*i+2] = NEG; ga[4*i+3] = NEG;
                gb[4*i+0] = NEG; gb[4*i+1] = NEG; gb[4*i+2] = NEG; gb[4*i+3] = NEG;
            }
        }
    }

    #pragma unroll
    for (int h = 0; h < 2; ++h) {
        const float* g = (h == 0) ? ga : gb;
        // balanced-tree max over g[4..16]
        const float t45   = fmaxf(g[4],  g[5]);
        const float t67   = fmaxf(g[6],  g[7]);
        const float t89   = fmaxf(g[8],  g[9]);
        const float t1011 = fmaxf(g[10], g[11]);
        const float t1213 = fmaxf(g[12], g[13]);
        const float t1415 = fmaxf(g[14], g[15]);
        const float q0 = fmaxf(t45,  t67);
        const float q1 = fmaxf(t89,  t1011);
        const float q2 = fmaxf(t1213, t1415);
        const float cm = fmaxf(fmaxf(q0, q1), fmaxf(q2, g[16]));

        const float a = fmaxf(g[2], g[3]);
        const float b = fmaxf(g[17], g[18]);
        const float m0 = fmaxf(cm, fmaxf(g[1], a));
        const float m1 = fmaxf(cm, fmaxf(a, g[17]));
        const float m2 = fmaxf(cm, fmaxf(g[3], b));
        const float m3 = fmaxf(cm, fmaxf(b, g[19]));

        float4 o;
        o.x = __saturatef(1.0f + (g[0] - m0));
        o.y = __saturatef(1.0f + (g[1] - m1));
        o.z = __saturatef(1.0f + (g[2] - m2));
        o.w = __saturatef(1.0f + (g[3] - m3));

        __stwt(reinterpret_cast<float4*>(out + c0 + h * HALF), o);  // write-through
    }
}

extern "C" void kernel_launch(void* const* d_in, const int* in_sizes, int n_in,
                              void* d_out, int out_size) {
    const float* in = (const float*)d_in[0];
    float* out = (float*)d_out;
    const int threads_total = HALF / 4;        // 524,288 threads
    shadow_dualwt<<<threads_total / THREADS, THREADS>>>(in, out);
}